// round 10
// baseline (speedup 1.0000x reference)
#include <cuda_runtime.h>
#include <cstddef>
#include <cstdint>

// Problem constants
#define BATCH   2048
#define NTOK    98
#define EMB     192
#define NHEADS  6
#define HDIM    32
#define NWIN    64
#define NN      (NTOK*NTOK)        // 9604
#define NCP     112                // padded key/col dim for attention tiles
#define NNP     (NTOK*NCP)         // 10976 padded bm row block

// Scratch (device globals — no allocation allowed)
__device__ float d_qkv[(size_t)BATCH * 3 * NHEADS * NTOK * HDIM];   // [b][which][h][n][d]
__device__ float d_attnout[(size_t)BATCH * NTOK * EMB];             // [b][n][h*32+d]
__device__ float d_bm[(size_t)NHEADS * NWIN * NNP];                 // bias+mask, padded cols

// ---------------------------------------------------------------------------
// helpers
// ---------------------------------------------------------------------------
__device__ __forceinline__ uint32_t f2tf32(float f) {
    uint32_t u;
    asm("cvt.rna.tf32.f32 %0, %1;" : "=r"(u) : "f"(f));
    return u;
}

__device__ __forceinline__ void mma_tf32(float c[4], const uint32_t a[4], const uint32_t b[2]) {
    asm volatile(
        "mma.sync.aligned.m16n8k8.row.col.f32.tf32.tf32.f32 "
        "{%0,%1,%2,%3},{%4,%5,%6,%7},{%8,%9},{%0,%1,%2,%3};"
        : "+f"(c[0]), "+f"(c[1]), "+f"(c[2]), "+f"(c[3])
        : "r"(a[0]), "r"(a[1]), "r"(a[2]), "r"(a[3]), "r"(b[0]), "r"(b[1]));
}

__device__ __forceinline__ void cp16(uint32_t dst, const void* src) {
    asm volatile("cp.async.cg.shared.global [%0], [%1], 16;" :: "r"(dst), "l"(src));
}
__device__ __forceinline__ void cp_commit() {
    asm volatile("cp.async.commit_group;");
}
template <int N> __device__ __forceinline__ void cp_wait() {
    asm volatile("cp.async.wait_group %0;" :: "n"(N));
}

__device__ __forceinline__ void cvt4_inplace(float* p) {
    float4 v = *(const float4*)p;
    uint4 u = make_uint4(f2tf32(v.x), f2tf32(v.y), f2tf32(v.z), f2tf32(v.w));
    *(uint4*)p = u;
}

// ---------------------------------------------------------------------------
// Kernel 1: combine bias + mask with column padding to NCP
// ---------------------------------------------------------------------------
__global__ void combine_bias_kernel(const float* __restrict__ table,
                                    const int* __restrict__ rel,
                                    const float* __restrict__ mask) {
    const int h = blockIdx.y;
    const int w = blockIdx.z;
    const int idx = blockIdx.x * blockDim.x + threadIdx.x;
    if (idx >= NNP) return;
    const int i = idx / NCP;
    const int j = idx - i * NCP;
    float v = -1e30f;
    if (j < NTOK)
        v = table[rel[i * NTOK + j] * NHEADS + h] + mask[(size_t)w * NN + i * NTOK + j];
    d_bm[((size_t)(h * NWIN + w)) * NNP + idx] = v;
}

// ---------------------------------------------------------------------------
// tf32 tensor-core GEMM: C[m, c] = A[m,:] . W[c,:] + bias[c]
// Block tile 256x64, K-tile 32, double-buffered cp.async. After each wait, a
// vectorized in-place cvt pass converts the tile to tf32 so the MMA inner
// loop is pure LDS+MMA (no per-fragment cvt).
// ---------------------------------------------------------------------------
#define KTILE 32
#define NKIT  6
#define ASTR  36
#define BSTR  36
#define AS_FLOATS (256 * ASTR)
#define BS_FLOATS (64 * BSTR)
#define GEMM_SMEM_BYTES ((AS_FLOATS + BS_FLOATS) * 2 * 4)

__device__ __forceinline__ void g_load_tiles(const float* __restrict__ A,
                                             const float* __restrict__ W,
                                             float* As, float* Bs,
                                             int m0, int n0, int kt, int tid) {
    const int r = tid >> 3;
    const int q = tid & 7;
    uint32_t as_base = (uint32_t)__cvta_generic_to_shared(As);
    uint32_t bs_base = (uint32_t)__cvta_generic_to_shared(Bs);
    #pragma unroll
    for (int it = 0; it < 8; it++) {
        int m = r + it * 32;
        cp16(as_base + (uint32_t)(m * ASTR + q * 4) * 4,
             A + (size_t)(m0 + m) * EMB + kt + q * 4);
    }
    #pragma unroll
    for (int it = 0; it < 2; it++) {
        int n = r + it * 32;
        cp16(bs_base + (uint32_t)(n * BSTR + q * 4) * 4,
             W + (size_t)(n0 + n) * EMB + kt + q * 4);
    }
    cp_commit();
}

// vectorized tf32 conversion pass: As 2048 float4 + Bs 512 float4, 10/thread
__device__ __forceinline__ void g_cvt_tiles(float* As, float* Bs, int tid) {
    #pragma unroll
    for (int i = 0; i < 10; i++) {
        int idx = tid + i * 256;
        if (idx < 2048) {
            int r = idx >> 3, q = idx & 7;
            cvt4_inplace(&As[r * ASTR + q * 4]);
        } else {
            int j = idx - 2048;
            int r = j >> 3, q = j & 7;
            cvt4_inplace(&Bs[r * BSTR + q * 4]);
        }
    }
}

__device__ __forceinline__ void g_compute(const float* As, const float* Bs,
                                          float acc[4][4][4], int lane,
                                          int wm, int wn) {
    #pragma unroll
    for (int ks = 0; ks < KTILE; ks += 8) {
        const int ka = ks + (lane & 3);
        uint32_t af[4][4];
        #pragma unroll
        for (int mt = 0; mt < 4; mt++) {
            const float* ap = As + (wm * 64 + mt * 16 + (lane >> 2)) * ASTR;
            af[mt][0] = __float_as_uint(ap[ka]);
            af[mt][1] = __float_as_uint(ap[8 * ASTR + ka]);
            af[mt][2] = __float_as_uint(ap[ka + 4]);
            af[mt][3] = __float_as_uint(ap[8 * ASTR + ka + 4]);
        }
        uint32_t bf[4][2];
        #pragma unroll
        for (int nt = 0; nt < 4; nt++) {
            const float* bp = Bs + (wn * 32 + nt * 8 + (lane >> 2)) * BSTR;
            bf[nt][0] = __float_as_uint(bp[ka]);
            bf[nt][1] = __float_as_uint(bp[ka + 4]);
        }
        #pragma unroll
        for (int mt = 0; mt < 4; mt++)
            #pragma unroll
            for (int nt = 0; nt < 4; nt++)
                mma_tf32(acc[mt][nt], af[mt], bf[nt]);
    }
}

__global__ __launch_bounds__(256, 2) void gemm_qkv_kernel(
    const float* __restrict__ A, const float* __restrict__ W,
    const float* __restrict__ bias) {
    extern __shared__ float sm[];
    float* As[2] = { sm, sm + AS_FLOATS };
    float* Bs[2] = { sm + 2 * AS_FLOATS, sm + 2 * AS_FLOATS + BS_FLOATS };

    const int tid = threadIdx.x;
    const int lane = tid & 31;
    const int wid = tid >> 5;
    const int wm = wid >> 1;
    const int wn = wid & 1;
    const int m0 = blockIdx.y * 256;
    const int n0 = blockIdx.x * 64;

    float acc[4][4][4];
    #pragma unroll
    for (int mt = 0; mt < 4; mt++)
        #pragma unroll
        for (int nt = 0; nt < 4; nt++)
            #pragma unroll
            for (int r = 0; r < 4; r++) acc[mt][nt][r] = 0.f;

    g_load_tiles(A, W, As[0], Bs[0], m0, n0, 0, tid);
    g_load_tiles(A, W, As[1], Bs[1], m0, n0, KTILE, tid);

    #pragma unroll
    for (int it = 0; it < NKIT; it++) {
        if (it < NKIT - 1) cp_wait<1>(); else cp_wait<0>();
        __syncthreads();
        g_cvt_tiles(As[it & 1], Bs[it & 1], tid);
        __syncthreads();
        g_compute(As[it & 1], Bs[it & 1], acc, lane, wm, wn);
        __syncthreads();
        if (it + 2 < NKIT)
            g_load_tiles(A, W, As[it & 1], Bs[it & 1], m0, n0, (it + 2) * KTILE, tid);
    }

    #pragma unroll
    for (int mt = 0; mt < 4; mt++) {
        #pragma unroll
        for (int half = 0; half < 2; half++) {
            int mg = m0 + wm * 64 + mt * 16 + (lane >> 2) + half * 8;
            int bb = mg / NTOK;
            int nn = mg - bb * NTOK;
            #pragma unroll
            for (int nt = 0; nt < 4; nt++) {
                int c = n0 + wn * 32 + nt * 8 + (lane & 3) * 2;
                int which = c / EMB;
                int rem = c - which * EMB;
                int h = rem >> 5;
                int d = rem & 31;
                size_t dst = ((((size_t)bb * 3 + which) * NHEADS + h) * NTOK + nn) * HDIM + d;
                float v0 = acc[mt][nt][half * 2 + 0] + bias[c];
                float v1 = acc[mt][nt][half * 2 + 1] + bias[c + 1];
                *(float2*)&d_qkv[dst] = make_float2(v0, v1);
            }
        }
    }
}

__global__ __launch_bounds__(256, 2) void gemm_proj_kernel(
    const float* __restrict__ W, const float* __restrict__ bias,
    float* __restrict__ out) {
    extern __shared__ float sm[];
    float* As[2] = { sm, sm + AS_FLOATS };
    float* Bs[2] = { sm + 2 * AS_FLOATS, sm + 2 * AS_FLOATS + BS_FLOATS };

    const int tid = threadIdx.x;
    const int lane = tid & 31;
    const int wid = tid >> 5;
    const int wm = wid >> 1;
    const int wn = wid & 1;
    const int m0 = blockIdx.y * 256;
    const int n0 = blockIdx.x * 64;

    float acc[4][4][4];
    #pragma unroll
    for (int mt = 0; mt < 4; mt++)
        #pragma unroll
        for (int nt = 0; nt < 4; nt++)
            #pragma unroll
            for (int r = 0; r < 4; r++) acc[mt][nt][r] = 0.f;

    const float* A = d_attnout;
    g_load_tiles(A, W, As[0], Bs[0], m0, n0, 0, tid);
    g_load_tiles(A, W, As[1], Bs[1], m0, n0, KTILE, tid);

    #pragma unroll
    for (int it = 0; it < NKIT; it++) {
        if (it < NKIT - 1) cp_wait<1>(); else cp_wait<0>();
        __syncthreads();
        g_cvt_tiles(As[it & 1], Bs[it & 1], tid);
        __syncthreads();
        g_compute(As[it & 1], Bs[it & 1], acc, lane, wm, wn);
        __syncthreads();
        if (it + 2 < NKIT)
            g_load_tiles(A, W, As[it & 1], Bs[it & 1], m0, n0, (it + 2) * KTILE, tid);
    }

    #pragma unroll
    for (int mt = 0; mt < 4; mt++) {
        #pragma unroll
        for (int half = 0; half < 2; half++) {
            int mg = m0 + wm * 64 + mt * 16 + (lane >> 2) + half * 8;
            #pragma unroll
            for (int nt = 0; nt < 4; nt++) {
                int c = n0 + wn * 32 + nt * 8 + (lane & 3) * 2;
                float v0 = acc[mt][nt][half * 2 + 0] + bias[c];
                float v1 = acc[mt][nt][half * 2 + 1] + bias[c + 1];
                *(float2*)&out[(size_t)mg * EMB + c] = make_float2(v0, v1);
            }
        }
    }
}

// ---------------------------------------------------------------------------
// Kernel 3: tensor-core attention. One CTA (128 thr, 4 warps) per (b, h).
// Q/K/V staged + pre-converted to tf32 in smem; bias+mask read directly from
// gmem (L2-resident); softmax in registers; P->A-frag permute via shfl.
// ---------------------------------------------------------------------------
#define QSTR 36
#define KSTR 36
#define VSTR 40
#define SQ_FLOATS (128 * QSTR)       // 4608
#define SK_FLOATS (NCP * KSTR)       // 4032
#define SV_FLOATS (NCP * VSTR)       // 4480
#define ATTN_SMEM_BYTES ((SQ_FLOATS + SK_FLOATS + SV_FLOATS) * 4)  // 52480

__global__ __launch_bounds__(128, 2) void attn_kernel() {
    extern __shared__ float sh[];
    float* sQ  = sh;
    float* sK  = sQ + SQ_FLOATS;
    float* sV  = sK + SK_FLOATS;

    const int t = threadIdx.x;
    const int lane = t & 31;
    const int w4 = t >> 5;          // warp 0..3

    const int bh = blockIdx.x;
    const int b = bh / NHEADS;
    const int h = bh - b * NHEADS;
    const int win = b & (NWIN - 1);

    const size_t base = (((size_t)b * 3) * NHEADS + h) * (NTOK * HDIM);
    const float* qg = d_qkv + base;
    const float* kg = qg + (size_t)NHEADS * NTOK * HDIM;
    const float* vg = qg + 2 * (size_t)NHEADS * NTOK * HDIM;
    const float* bmg = d_bm + (size_t)(h * NWIN + win) * NNP;

    // ---- stage Q/K/V via cp.async, zero pad rows, then vectorized tf32 cvt ----
    {
        uint32_t uQ = (uint32_t)__cvta_generic_to_shared(sQ);
        uint32_t uK = (uint32_t)__cvta_generic_to_shared(sK);
        uint32_t uV = (uint32_t)__cvta_generic_to_shared(sV);
        for (int idx = t; idx < NTOK * 8; idx += 128) {
            int r = idx >> 3, q = (idx & 7) * 4;
            cp16(uQ + (uint32_t)(r * QSTR + q) * 4, qg + r * HDIM + q);
            cp16(uK + (uint32_t)(r * KSTR + q) * 4, kg + r * HDIM + q);
            cp16(uV + (uint32_t)(r * VSTR + q) * 4, vg + r * HDIM + q);
        }
        cp_commit();
        float4 z = make_float4(0.f, 0.f, 0.f, 0.f);
        for (int idx = t; idx < 30 * 8; idx += 128) {
            int r = 98 + (idx >> 3), c = (idx & 7) * 4;
            *(float4*)&sQ[r * QSTR + c] = z;
        }
        for (int idx = t; idx < 14 * 8; idx += 128) {
            int r = 98 + (idx >> 3), c = (idx & 7) * 4;
            *(float4*)&sK[r * KSTR + c] = z;
        }
        for (int idx = t; idx < 14 * 8; idx += 128) {
            int r = 98 + (idx >> 3), c = (idx & 7) * 4;
            *(float4*)&sV[r * VSTR + c] = z;
        }
        cp_wait<0>();
        __syncthreads();
        // cvt: Q 1024 f4, K 896 f4, V 896 f4 = 2816 = 22 * 128
        #pragma unroll
        for (int i = 0; i < 22; i++) {
            int idx = t + i * 128;
            if (idx < 1024) {
                int r = idx >> 3, q = (idx & 7) * 4;
                cvt4_inplace(&sQ[r * QSTR + q]);
            } else if (idx < 1920) {
                int j = idx - 1024;
                int r = j >> 3, q = (j & 7) * 4;
                cvt4_inplace(&sK[r * KSTR + q]);
            } else {
                int j = idx - 1920;
                int r = j >> 3, q = (j & 7) * 4;
                cvt4_inplace(&sV[r * VSTR + q]);
            }
        }
        __syncthreads();
    }

    const int g = lane >> 2;        // quad row
    const int c = lane & 3;         // quad pos

    // ---- S = Q K^T : c-frags sf[2][14][4] ----
    float sf[2][14][4];
    #pragma unroll
    for (int mt = 0; mt < 2; mt++)
        #pragma unroll
        for (int nt = 0; nt < 14; nt++)
            #pragma unroll
            for (int r = 0; r < 4; r++) sf[mt][nt][r] = 0.f;

    #pragma unroll
    for (int ks = 0; ks < 4; ks++) {
        const int k = ks * 8 + c;
        uint32_t af[2][4];
        #pragma unroll
        for (int mt = 0; mt < 2; mt++) {
            const float* ap = sQ + (w4 * 32 + mt * 16 + g) * QSTR;
            af[mt][0] = __float_as_uint(ap[k]);
            af[mt][1] = __float_as_uint(ap[8 * QSTR + k]);
            af[mt][2] = __float_as_uint(ap[k + 4]);
            af[mt][3] = __float_as_uint(ap[8 * QSTR + k + 4]);
        }
        #pragma unroll
        for (int nt = 0; nt < 14; nt++) {
            const float* bp = sK + (nt * 8 + g) * KSTR;
            uint32_t bf[2];
            bf[0] = __float_as_uint(bp[k]);
            bf[1] = __float_as_uint(bp[k + 4]);
            mma_tf32(sf[0][nt], af[0], bf);
            mma_tf32(sf[1][nt], af[1], bf);
        }
    }

    // ---- scale + bias/mask (direct gmem) + row max ----
    const float scale = 0.17677669529663687f;  // 32^-0.5
    float mx[2][2];
    #pragma unroll
    for (int mt = 0; mt < 2; mt++) { mx[mt][0] = -1e30f; mx[mt][1] = -1e30f; }

    #pragma unroll
    for (int mt = 0; mt < 2; mt++) {
        int r0 = w4 * 32 + mt * 16 + g;
        int r0c = min(r0, NTOK - 1);
        int r1c = min(r0 + 8, NTOK - 1);
        const float* bm0 = bmg + (size_t)r0c * NCP;
        const float* bm1 = bmg + (size_t)r1c * NCP;
        #pragma unroll
        for (int nt = 0; nt < 14; nt++) {
            int col = nt * 8 + c * 2;
            float2 b0 = *(const float2*)&bm0[col];
            float2 b1 = *(const float2*)&bm1[col];
            sf[mt][nt][0] = fmaf(sf[mt][nt][0], scale, b0.x);
            sf[mt][nt][1] = fmaf(sf[mt][nt][1], scale, b0.y);
            sf[mt][nt][2] = fmaf(sf[mt][nt][2], scale, b1.x);
            sf[mt][nt][3] = fmaf(sf[mt][nt][3], scale, b1.y);
            mx[mt][0] = fmaxf(mx[mt][0], fmaxf(sf[mt][nt][0], sf[mt][nt][1]));
            mx[mt][1] = fmaxf(mx[mt][1], fmaxf(sf[mt][nt][2], sf[mt][nt][3]));
        }
    }
    #pragma unroll
    for (int mt = 0; mt < 2; mt++)
        #pragma unroll
        for (int hf = 0; hf < 2; hf++) {
            float v = mx[mt][hf];
            v = fmaxf(v, __shfl_xor_sync(0xffffffffu, v, 1));
            v = fmaxf(v, __shfl_xor_sync(0xffffffffu, v, 2));
            mx[mt][hf] = v;
        }

    // ---- exp + row sum ----
    float sum[2][2] = {{0.f, 0.f}, {0.f, 0.f}};
    #pragma unroll
    for (int mt = 0; mt < 2; mt++)
        #pragma unroll
        for (int nt = 0; nt < 14; nt++) {
            float p0 = __expf(sf[mt][nt][0] - mx[mt][0]);
            float p1 = __expf(sf[mt][nt][1] - mx[mt][0]);
            float p2 = __expf(sf[mt][nt][2] - mx[mt][1]);
            float p3 = __expf(sf[mt][nt][3] - mx[mt][1]);
            sf[mt][nt][0] = p0; sf[mt][nt][1] = p1;
            sf[mt][nt][2] = p2; sf[mt][nt][3] = p3;
            sum[mt][0] += p0 + p1;
            sum[mt][1] += p2 + p3;
        }
    #pragma unroll
    for (int mt = 0; mt < 2; mt++)
        #pragma unroll
        for (int hf = 0; hf < 2; hf++) {
            float v = sum[mt][hf];
            v += __shfl_xor_sync(0xffffffffu, v, 1);
            v += __shfl_xor_sync(0xffffffffu, v, 2);
            sum[mt][hf] = v;
        }

    // ---- O = P V ----
    float of[2][4][4];
    #pragma unroll
    for (int mt = 0; mt < 2; mt++)
        #pragma unroll
        for (int nt = 0; nt < 4; nt++)
            #pragma unroll
            for (int r = 0; r < 4; r++) of[mt][nt][r] = 0.f;

    const int srcA = (lane & ~3) | (c >> 1);
    const int srcB = srcA + 2;

    #pragma unroll
    for (int kt = 0; kt < 14; kt++) {
        uint32_t pa[2][4];
        #pragma unroll
        for (int mt = 0; mt < 2; mt++) {
            float x0 = __shfl_sync(0xffffffffu, sf[mt][kt][0], srcA);
            float x1 = __shfl_sync(0xffffffffu, sf[mt][kt][1], srcA);
            float y0 = __shfl_sync(0xffffffffu, sf[mt][kt][0], srcB);
            float y1 = __shfl_sync(0xffffffffu, sf[mt][kt][1], srcB);
            float z0 = __shfl_sync(0xffffffffu, sf[mt][kt][2], srcA);
            float z1 = __shfl_sync(0xffffffffu, sf[mt][kt][3], srcA);
            float u0 = __shfl_sync(0xffffffffu, sf[mt][kt][2], srcB);
            float u1 = __shfl_sync(0xffffffffu, sf[mt][kt][3], srcB);
            pa[mt][0] = f2tf32((c & 1) ? x1 : x0);
            pa[mt][1] = f2tf32((c & 1) ? z1 : z0);
            pa[mt][2] = f2tf32((c & 1) ? y1 : y0);
            pa[mt][3] = f2tf32((c & 1) ? u1 : u0);
        }
        #pragma unroll
        for (int nt = 0; nt < 4; nt++) {
            const float* vp = sV + (kt * 8 + c) * VSTR + nt * 8 + g;
            uint32_t bf[2];
            bf[0] = __float_as_uint(vp[0]);
            bf[1] = __float_as_uint(vp[4 * VSTR]);
            mma_tf32(of[0][nt], pa[0], bf);
            mma_tf32(of[1][nt], pa[1], bf);
        }
    }

    // ---- epilogue: normalize + store ----
    #pragma unroll
    for (int mt = 0; mt < 2; mt++) {
        #pragma unroll
        for (int hf = 0; hf < 2; hf++) {
            int row = w4 * 32 + mt * 16 + g + hf * 8;
            if (row < NTOK) {
                float inv = 1.f / sum[mt][hf];
                float* op = d_attnout + ((size_t)b * NTOK + row) * EMB + h * HDIM;
                #pragma unroll
                for (int nt = 0; nt < 4; nt++) {
                    int col = nt * 8 + c * 2;
                    float v0 = of[mt][nt][hf * 2 + 0] * inv;
                    float v1 = of[mt][nt][hf * 2 + 1] * inv;
                    *(float2*)&op[col] = make_float2(v0, v1);
                }
            }
        }
    }
}

// ---------------------------------------------------------------------------
// Launch
// ---------------------------------------------------------------------------
extern "C" void kernel_launch(void* const* d_in, const int* in_sizes, int n_in,
                              void* d_out, int out_size) {
    const float* x          = (const float*)d_in[0];
    const float* mask       = (const float*)d_in[1];
    const float* qkv_w      = (const float*)d_in[2];
    const float* qkv_b      = (const float*)d_in[3];
    const float* o_w        = (const float*)d_in[4];
    const float* o_b        = (const float*)d_in[5];
    const float* bias_table = (const float*)d_in[6];
    const int*   rel_index  = (const int*)d_in[7];
    float* out = (float*)d_out;

    cudaFuncSetAttribute(gemm_qkv_kernel,
        cudaFuncAttributeMaxDynamicSharedMemorySize, GEMM_SMEM_BYTES);
    cudaFuncSetAttribute(gemm_proj_kernel,
        cudaFuncAttributeMaxDynamicSharedMemorySize, GEMM_SMEM_BYTES);
    cudaFuncSetAttribute(attn_kernel,
        cudaFuncAttributeMaxDynamicSharedMemorySize, ATTN_SMEM_BYTES);

    combine_bias_kernel<<<dim3((NNP + 255) / 256, NHEADS, NWIN), 256>>>(
        bias_table, rel_index, mask);

    // QKV: M = 200704 (784 tiles of 256), Ncols = 576 (9 tiles of 64)
    gemm_qkv_kernel<<<dim3(9, 784), 256, GEMM_SMEM_BYTES>>>(x, qkv_w, qkv_b);

    // Attention: one CTA per (b, h)
    attn_kernel<<<BATCH * NHEADS, 128, ATTN_SMEM_BYTES>>>();

    // Projection: Ncols = 192 (3 tiles of 64)
    gemm_proj_kernel<<<dim3(3, 784), 256, GEMM_SMEM_BYTES>>>(o_w, o_b, out);
}

// round 11
// speedup vs baseline: 1.1437x; 1.1437x over previous
#include <cuda_runtime.h>
#include <cstddef>
#include <cstdint>

// Problem constants
#define BATCH   2048
#define NTOK    98
#define EMB     192
#define NHEADS  6
#define HDIM    32
#define NWIN    64
#define NN      (NTOK*NTOK)        // 9604
#define NCP     112                // padded key/col dim for attention tiles
#define NNP     (NTOK*NCP)         // 10976 padded bm row block
#define MROWS   (BATCH*NTOK)       // 200704

// Scratch (device globals — no allocation allowed)
__device__ float d_qkv[(size_t)BATCH * 3 * NHEADS * NTOK * HDIM];   // tf32-rounded [b][which][h][n][d]
__device__ float d_attnout[(size_t)BATCH * NTOK * EMB];             // tf32-rounded [b][n][h*32+d]
__device__ float d_bm[(size_t)NHEADS * NWIN * NNP];                 // bias+mask fp32, padded cols
__device__ float d_xt[(size_t)MROWS * EMB];                         // tf32-rounded x
__device__ float d_wq[3 * EMB * EMB];                               // tf32-rounded qkv_w
__device__ float d_wo[EMB * EMB];                                   // tf32-rounded o_w

// ---------------------------------------------------------------------------
// helpers
// ---------------------------------------------------------------------------
__device__ __forceinline__ uint32_t f2tf32(float f) {
    uint32_t u;
    asm("cvt.rna.tf32.f32 %0, %1;" : "=r"(u) : "f"(f));
    return u;
}

__device__ __forceinline__ void mma_tf32(float c[4], const uint32_t a[4], const uint32_t b[2]) {
    asm volatile(
        "mma.sync.aligned.m16n8k8.row.col.f32.tf32.tf32.f32 "
        "{%0,%1,%2,%3},{%4,%5,%6,%7},{%8,%9},{%0,%1,%2,%3};"
        : "+f"(c[0]), "+f"(c[1]), "+f"(c[2]), "+f"(c[3])
        : "r"(a[0]), "r"(a[1]), "r"(a[2]), "r"(a[3]), "r"(b[0]), "r"(b[1]));
}

__device__ __forceinline__ void cp16(uint32_t dst, const void* src) {
    asm volatile("cp.async.cg.shared.global [%0], [%1], 16;" :: "r"(dst), "l"(src));
}
__device__ __forceinline__ void cp_commit() {
    asm volatile("cp.async.commit_group;");
}
template <int N> __device__ __forceinline__ void cp_wait() {
    asm volatile("cp.async.wait_group %0;" :: "n"(N));
}

// ---------------------------------------------------------------------------
// Kernel 0a: convert x -> tf32 bit patterns (float4 grid-stride)
// ---------------------------------------------------------------------------
__global__ void cvt_x_kernel(const float* __restrict__ x) {
    const int n4 = MROWS * EMB / 4;   // 9,633,792
    for (int i = blockIdx.x * blockDim.x + threadIdx.x; i < n4;
         i += gridDim.x * blockDim.x) {
        float4 v = ((const float4*)x)[i];
        uint4 u = make_uint4(f2tf32(v.x), f2tf32(v.y), f2tf32(v.z), f2tf32(v.w));
        ((uint4*)d_xt)[i] = u;
    }
}

// Kernel 0b: convert weights -> tf32
__global__ void cvt_w_kernel(const float* __restrict__ qkv_w,
                             const float* __restrict__ o_w) {
    const int nq = 3 * EMB * EMB / 4;  // 27648
    const int no = EMB * EMB / 4;      // 9216
    for (int i = blockIdx.x * blockDim.x + threadIdx.x; i < nq + no;
         i += gridDim.x * blockDim.x) {
        if (i < nq) {
            float4 v = ((const float4*)qkv_w)[i];
            ((uint4*)d_wq)[i] = make_uint4(f2tf32(v.x), f2tf32(v.y), f2tf32(v.z), f2tf32(v.w));
        } else {
            int j = i - nq;
            float4 v = ((const float4*)o_w)[j];
            ((uint4*)d_wo)[j] = make_uint4(f2tf32(v.x), f2tf32(v.y), f2tf32(v.z), f2tf32(v.w));
        }
    }
}

// ---------------------------------------------------------------------------
// Kernel 1: combine bias + mask with column padding to NCP
// ---------------------------------------------------------------------------
__global__ void combine_bias_kernel(const float* __restrict__ table,
                                    const int* __restrict__ rel,
                                    const float* __restrict__ mask) {
    const int h = blockIdx.y;
    const int w = blockIdx.z;
    const int idx = blockIdx.x * blockDim.x + threadIdx.x;
    if (idx >= NNP) return;
    const int i = idx / NCP;
    const int j = idx - i * NCP;
    float v = -1e30f;
    if (j < NTOK)
        v = table[rel[i * NTOK + j] * NHEADS + h] + mask[(size_t)w * NN + i * NTOK + j];
    d_bm[((size_t)(h * NWIN + w)) * NNP + idx] = v;
}

// ---------------------------------------------------------------------------
// tf32 tensor-core GEMM, inputs pre-converted to tf32 in gmem.
// Block tile 256x64, K-tile 32, double-buffered cp.async.
// Inner loop: pure LDS + MMA (no cvt).
// ---------------------------------------------------------------------------
#define KTILE 32
#define NKIT  6
#define ASTR  36
#define BSTR  36
#define AS_FLOATS (256 * ASTR)
#define BS_FLOATS (64 * BSTR)
#define GEMM_SMEM_BYTES ((AS_FLOATS + BS_FLOATS) * 2 * 4)

__device__ __forceinline__ void g_load_tiles(const float* __restrict__ A,
                                             const float* __restrict__ W,
                                             float* As, float* Bs,
                                             int m0, int n0, int kt, int tid) {
    const int r = tid >> 3;
    const int q = tid & 7;
    uint32_t as_base = (uint32_t)__cvta_generic_to_shared(As);
    uint32_t bs_base = (uint32_t)__cvta_generic_to_shared(Bs);
    #pragma unroll
    for (int it = 0; it < 8; it++) {
        int m = r + it * 32;
        cp16(as_base + (uint32_t)(m * ASTR + q * 4) * 4,
             A + (size_t)(m0 + m) * EMB + kt + q * 4);
    }
    #pragma unroll
    for (int it = 0; it < 2; it++) {
        int n = r + it * 32;
        cp16(bs_base + (uint32_t)(n * BSTR + q * 4) * 4,
             W + (size_t)(n0 + n) * EMB + kt + q * 4);
    }
    cp_commit();
}

__device__ __forceinline__ void g_compute(const float* As, const float* Bs,
                                          float acc[4][4][4], int lane,
                                          int wm, int wn) {
    #pragma unroll
    for (int ks = 0; ks < KTILE; ks += 8) {
        const int ka = ks + (lane & 3);
        uint32_t af[4][4];
        #pragma unroll
        for (int mt = 0; mt < 4; mt++) {
            const float* ap = As + (wm * 64 + mt * 16 + (lane >> 2)) * ASTR;
            af[mt][0] = __float_as_uint(ap[ka]);
            af[mt][1] = __float_as_uint(ap[8 * ASTR + ka]);
            af[mt][2] = __float_as_uint(ap[ka + 4]);
            af[mt][3] = __float_as_uint(ap[8 * ASTR + ka + 4]);
        }
        uint32_t bf[4][2];
        #pragma unroll
        for (int nt = 0; nt < 4; nt++) {
            const float* bp = Bs + (wn * 32 + nt * 8 + (lane >> 2)) * BSTR;
            bf[nt][0] = __float_as_uint(bp[ka]);
            bf[nt][1] = __float_as_uint(bp[ka + 4]);
        }
        #pragma unroll
        for (int mt = 0; mt < 4; mt++)
            #pragma unroll
            for (int nt = 0; nt < 4; nt++)
                mma_tf32(acc[mt][nt], af[mt], bf[nt]);
    }
}

// QKV variant: epilogue rounds (acc + bias) to tf32 and permutes into d_qkv
__global__ __launch_bounds__(256, 2) void gemm_qkv_kernel(
    const float* __restrict__ bias) {
    extern __shared__ float sm[];
    float* As[2] = { sm, sm + AS_FLOATS };
    float* Bs[2] = { sm + 2 * AS_FLOATS, sm + 2 * AS_FLOATS + BS_FLOATS };

    const int tid = threadIdx.x;
    const int lane = tid & 31;
    const int wid = tid >> 5;
    const int wm = wid >> 1;
    const int wn = wid & 1;
    const int m0 = blockIdx.y * 256;
    const int n0 = blockIdx.x * 64;

    float acc[4][4][4];
    #pragma unroll
    for (int mt = 0; mt < 4; mt++)
        #pragma unroll
        for (int nt = 0; nt < 4; nt++)
            #pragma unroll
            for (int r = 0; r < 4; r++) acc[mt][nt][r] = 0.f;

    const float* A = d_xt;
    const float* W = d_wq;
    g_load_tiles(A, W, As[0], Bs[0], m0, n0, 0, tid);
    g_load_tiles(A, W, As[1], Bs[1], m0, n0, KTILE, tid);

    #pragma unroll
    for (int it = 0; it < NKIT; it++) {
        if (it < NKIT - 1) cp_wait<1>(); else cp_wait<0>();
        __syncthreads();
        g_compute(As[it & 1], Bs[it & 1], acc, lane, wm, wn);
        __syncthreads();
        if (it + 2 < NKIT)
            g_load_tiles(A, W, As[it & 1], Bs[it & 1], m0, n0, (it + 2) * KTILE, tid);
    }

    #pragma unroll
    for (int mt = 0; mt < 4; mt++) {
        #pragma unroll
        for (int half = 0; half < 2; half++) {
            int mg = m0 + wm * 64 + mt * 16 + (lane >> 2) + half * 8;
            int bb = mg / NTOK;
            int nn = mg - bb * NTOK;
            #pragma unroll
            for (int nt = 0; nt < 4; nt++) {
                int c = n0 + wn * 32 + nt * 8 + (lane & 3) * 2;
                int which = c / EMB;
                int rem = c - which * EMB;
                int h = rem >> 5;
                int d = rem & 31;
                size_t dst = ((((size_t)bb * 3 + which) * NHEADS + h) * NTOK + nn) * HDIM + d;
                float v0 = __uint_as_float(f2tf32(acc[mt][nt][half * 2 + 0] + bias[c]));
                float v1 = __uint_as_float(f2tf32(acc[mt][nt][half * 2 + 1] + bias[c + 1]));
                *(float2*)&d_qkv[dst] = make_float2(v0, v1);
            }
        }
    }
}

// Projection variant: fp32 store to final output
__global__ __launch_bounds__(256, 2) void gemm_proj_kernel(
    const float* __restrict__ bias, float* __restrict__ out) {
    extern __shared__ float sm[];
    float* As[2] = { sm, sm + AS_FLOATS };
    float* Bs[2] = { sm + 2 * AS_FLOATS, sm + 2 * AS_FLOATS + BS_FLOATS };

    const int tid = threadIdx.x;
    const int lane = tid & 31;
    const int wid = tid >> 5;
    const int wm = wid >> 1;
    const int wn = wid & 1;
    const int m0 = blockIdx.y * 256;
    const int n0 = blockIdx.x * 64;

    float acc[4][4][4];
    #pragma unroll
    for (int mt = 0; mt < 4; mt++)
        #pragma unroll
        for (int nt = 0; nt < 4; nt++)
            #pragma unroll
            for (int r = 0; r < 4; r++) acc[mt][nt][r] = 0.f;

    const float* A = d_attnout;
    const float* W = d_wo;
    g_load_tiles(A, W, As[0], Bs[0], m0, n0, 0, tid);
    g_load_tiles(A, W, As[1], Bs[1], m0, n0, KTILE, tid);

    #pragma unroll
    for (int it = 0; it < NKIT; it++) {
        if (it < NKIT - 1) cp_wait<1>(); else cp_wait<0>();
        __syncthreads();
        g_compute(As[it & 1], Bs[it & 1], acc, lane, wm, wn);
        __syncthreads();
        if (it + 2 < NKIT)
            g_load_tiles(A, W, As[it & 1], Bs[it & 1], m0, n0, (it + 2) * KTILE, tid);
    }

    #pragma unroll
    for (int mt = 0; mt < 4; mt++) {
        #pragma unroll
        for (int half = 0; half < 2; half++) {
            int mg = m0 + wm * 64 + mt * 16 + (lane >> 2) + half * 8;
            #pragma unroll
            for (int nt = 0; nt < 4; nt++) {
                int c = n0 + wn * 32 + nt * 8 + (lane & 3) * 2;
                float v0 = acc[mt][nt][half * 2 + 0] + bias[c];
                float v1 = acc[mt][nt][half * 2 + 1] + bias[c + 1];
                *(float2*)&out[(size_t)mg * EMB + c] = make_float2(v0, v1);
            }
        }
    }
}

// ---------------------------------------------------------------------------
// Kernel 3: tensor-core attention. One CTA (128 thr, 4 warps) per (b, h).
// d_qkv already tf32-rounded: stage + mma directly, no cvt pass.
// bias+mask read directly from gmem (L2-resident). Epilogue stores
// tf32-rounded d_attnout for the proj GEMM.
// ---------------------------------------------------------------------------
#define QSTR 36
#define KSTR 36
#define VSTR 40
#define SQ_FLOATS (128 * QSTR)       // 4608
#define SK_FLOATS (NCP * KSTR)       // 4032
#define SV_FLOATS (NCP * VSTR)       // 4480
#define ATTN_SMEM_BYTES ((SQ_FLOATS + SK_FLOATS + SV_FLOATS) * 4)  // 52480

__global__ __launch_bounds__(128, 2) void attn_kernel() {
    extern __shared__ float sh[];
    float* sQ  = sh;
    float* sK  = sQ + SQ_FLOATS;
    float* sV  = sK + SK_FLOATS;

    const int t = threadIdx.x;
    const int lane = t & 31;
    const int w4 = t >> 5;          // warp 0..3

    const int bh = blockIdx.x;
    const int b = bh / NHEADS;
    const int h = bh - b * NHEADS;
    const int win = b & (NWIN - 1);

    const size_t base = (((size_t)b * 3) * NHEADS + h) * (NTOK * HDIM);
    const float* qg = d_qkv + base;
    const float* kg = qg + (size_t)NHEADS * NTOK * HDIM;
    const float* vg = qg + 2 * (size_t)NHEADS * NTOK * HDIM;
    const float* bmg = d_bm + (size_t)(h * NWIN + win) * NNP;

    // ---- stage Q/K/V via cp.async (already tf32), zero pad rows ----
    {
        uint32_t uQ = (uint32_t)__cvta_generic_to_shared(sQ);
        uint32_t uK = (uint32_t)__cvta_generic_to_shared(sK);
        uint32_t uV = (uint32_t)__cvta_generic_to_shared(sV);
        for (int idx = t; idx < NTOK * 8; idx += 128) {
            int r = idx >> 3, q = (idx & 7) * 4;
            cp16(uQ + (uint32_t)(r * QSTR + q) * 4, qg + r * HDIM + q);
            cp16(uK + (uint32_t)(r * KSTR + q) * 4, kg + r * HDIM + q);
            cp16(uV + (uint32_t)(r * VSTR + q) * 4, vg + r * HDIM + q);
        }
        cp_commit();
        float4 z = make_float4(0.f, 0.f, 0.f, 0.f);
        for (int idx = t; idx < 30 * 8; idx += 128) {
            int r = 98 + (idx >> 3), c = (idx & 7) * 4;
            *(float4*)&sQ[r * QSTR + c] = z;
        }
        for (int idx = t; idx < 14 * 8; idx += 128) {
            int r = 98 + (idx >> 3), c = (idx & 7) * 4;
            *(float4*)&sK[r * KSTR + c] = z;
        }
        for (int idx = t; idx < 14 * 8; idx += 128) {
            int r = 98 + (idx >> 3), c = (idx & 7) * 4;
            *(float4*)&sV[r * VSTR + c] = z;
        }
        cp_wait<0>();
        __syncthreads();
    }

    const int g = lane >> 2;        // quad row
    const int c = lane & 3;         // quad pos

    // ---- S = Q K^T : c-frags sf[2][14][4] ----
    float sf[2][14][4];
    #pragma unroll
    for (int mt = 0; mt < 2; mt++)
        #pragma unroll
        for (int nt = 0; nt < 14; nt++)
            #pragma unroll
            for (int r = 0; r < 4; r++) sf[mt][nt][r] = 0.f;

    #pragma unroll
    for (int ks = 0; ks < 4; ks++) {
        const int k = ks * 8 + c;
        uint32_t af[2][4];
        #pragma unroll
        for (int mt = 0; mt < 2; mt++) {
            const float* ap = sQ + (w4 * 32 + mt * 16 + g) * QSTR;
            af[mt][0] = __float_as_uint(ap[k]);
            af[mt][1] = __float_as_uint(ap[8 * QSTR + k]);
            af[mt][2] = __float_as_uint(ap[k + 4]);
            af[mt][3] = __float_as_uint(ap[8 * QSTR + k + 4]);
        }
        #pragma unroll
        for (int nt = 0; nt < 14; nt++) {
            const float* bp = sK + (nt * 8 + g) * KSTR;
            uint32_t bf[2];
            bf[0] = __float_as_uint(bp[k]);
            bf[1] = __float_as_uint(bp[k + 4]);
            mma_tf32(sf[0][nt], af[0], bf);
            mma_tf32(sf[1][nt], af[1], bf);
        }
    }

    // ---- scale + bias/mask (direct gmem) + row max ----
    const float scale = 0.17677669529663687f;  // 32^-0.5
    float mx[2][2];
    #pragma unroll
    for (int mt = 0; mt < 2; mt++) { mx[mt][0] = -1e30f; mx[mt][1] = -1e30f; }

    #pragma unroll
    for (int mt = 0; mt < 2; mt++) {
        int r0 = w4 * 32 + mt * 16 + g;
        int r0c = min(r0, NTOK - 1);
        int r1c = min(r0 + 8, NTOK - 1);
        const float* bm0 = bmg + (size_t)r0c * NCP;
        const float* bm1 = bmg + (size_t)r1c * NCP;
        #pragma unroll
        for (int nt = 0; nt < 14; nt++) {
            int col = nt * 8 + c * 2;
            float2 b0 = *(const float2*)&bm0[col];
            float2 b1 = *(const float2*)&bm1[col];
            sf[mt][nt][0] = fmaf(sf[mt][nt][0], scale, b0.x);
            sf[mt][nt][1] = fmaf(sf[mt][nt][1], scale, b0.y);
            sf[mt][nt][2] = fmaf(sf[mt][nt][2], scale, b1.x);
            sf[mt][nt][3] = fmaf(sf[mt][nt][3], scale, b1.y);
            mx[mt][0] = fmaxf(mx[mt][0], fmaxf(sf[mt][nt][0], sf[mt][nt][1]));
            mx[mt][1] = fmaxf(mx[mt][1], fmaxf(sf[mt][nt][2], sf[mt][nt][3]));
        }
    }
    #pragma unroll
    for (int mt = 0; mt < 2; mt++)
        #pragma unroll
        for (int hf = 0; hf < 2; hf++) {
            float v = mx[mt][hf];
            v = fmaxf(v, __shfl_xor_sync(0xffffffffu, v, 1));
            v = fmaxf(v, __shfl_xor_sync(0xffffffffu, v, 2));
            mx[mt][hf] = v;
        }

    // ---- exp + row sum ----
    float sum[2][2] = {{0.f, 0.f}, {0.f, 0.f}};
    #pragma unroll
    for (int mt = 0; mt < 2; mt++)
        #pragma unroll
        for (int nt = 0; nt < 14; nt++) {
            float p0 = __expf(sf[mt][nt][0] - mx[mt][0]);
            float p1 = __expf(sf[mt][nt][1] - mx[mt][0]);
            float p2 = __expf(sf[mt][nt][2] - mx[mt][1]);
            float p3 = __expf(sf[mt][nt][3] - mx[mt][1]);
            sf[mt][nt][0] = p0; sf[mt][nt][1] = p1;
            sf[mt][nt][2] = p2; sf[mt][nt][3] = p3;
            sum[mt][0] += p0 + p1;
            sum[mt][1] += p2 + p3;
        }
    #pragma unroll
    for (int mt = 0; mt < 2; mt++)
        #pragma unroll
        for (int hf = 0; hf < 2; hf++) {
            float v = sum[mt][hf];
            v += __shfl_xor_sync(0xffffffffu, v, 1);
            v += __shfl_xor_sync(0xffffffffu, v, 2);
            sum[mt][hf] = v;
        }

    // ---- O = P V ----
    float of[2][4][4];
    #pragma unroll
    for (int mt = 0; mt < 2; mt++)
        #pragma unroll
        for (int nt = 0; nt < 4; nt++)
            #pragma unroll
            for (int r = 0; r < 4; r++) of[mt][nt][r] = 0.f;

    const int srcA = (lane & ~3) | (c >> 1);
    const int srcB = srcA + 2;

    #pragma unroll
    for (int kt = 0; kt < 14; kt++) {
        uint32_t pa[2][4];
        #pragma unroll
        for (int mt = 0; mt < 2; mt++) {
            float x0 = __shfl_sync(0xffffffffu, sf[mt][kt][0], srcA);
            float x1 = __shfl_sync(0xffffffffu, sf[mt][kt][1], srcA);
            float y0 = __shfl_sync(0xffffffffu, sf[mt][kt][0], srcB);
            float y1 = __shfl_sync(0xffffffffu, sf[mt][kt][1], srcB);
            float z0 = __shfl_sync(0xffffffffu, sf[mt][kt][2], srcA);
            float z1 = __shfl_sync(0xffffffffu, sf[mt][kt][3], srcA);
            float u0 = __shfl_sync(0xffffffffu, sf[mt][kt][2], srcB);
            float u1 = __shfl_sync(0xffffffffu, sf[mt][kt][3], srcB);
            pa[mt][0] = f2tf32((c & 1) ? x1 : x0);
            pa[mt][1] = f2tf32((c & 1) ? z1 : z0);
            pa[mt][2] = f2tf32((c & 1) ? y1 : y0);
            pa[mt][3] = f2tf32((c & 1) ? u1 : u0);
        }
        #pragma unroll
        for (int nt = 0; nt < 4; nt++) {
            const float* vp = sV + (kt * 8 + c) * VSTR + nt * 8 + g;
            uint32_t bf[2];
            bf[0] = __float_as_uint(vp[0]);
            bf[1] = __float_as_uint(vp[4 * VSTR]);
            mma_tf32(of[0][nt], pa[0], bf);
            mma_tf32(of[1][nt], pa[1], bf);
        }
    }

    // ---- epilogue: normalize, round to tf32 for proj, store ----
    #pragma unroll
    for (int mt = 0; mt < 2; mt++) {
        #pragma unroll
        for (int hf = 0; hf < 2; hf++) {
            int row = w4 * 32 + mt * 16 + g + hf * 8;
            if (row < NTOK) {
                float inv = 1.f / sum[mt][hf];
                float* op = d_attnout + ((size_t)b * NTOK + row) * EMB + h * HDIM;
                #pragma unroll
                for (int nt = 0; nt < 4; nt++) {
                    int col = nt * 8 + c * 2;
                    float v0 = __uint_as_float(f2tf32(of[mt][nt][hf * 2 + 0] * inv));
                    float v1 = __uint_as_float(f2tf32(of[mt][nt][hf * 2 + 1] * inv));
                    *(float2*)&op[col] = make_float2(v0, v1);
                }
            }
        }
    }
}

// ---------------------------------------------------------------------------
// Launch
// ---------------------------------------------------------------------------
extern "C" void kernel_launch(void* const* d_in, const int* in_sizes, int n_in,
                              void* d_out, int out_size) {
    const float* x          = (const float*)d_in[0];
    const float* mask       = (const float*)d_in[1];
    const float* qkv_w      = (const float*)d_in[2];
    const float* qkv_b      = (const float*)d_in[3];
    const float* o_w        = (const float*)d_in[4];
    const float* o_b        = (const float*)d_in[5];
    const float* bias_table = (const float*)d_in[6];
    const int*   rel_index  = (const int*)d_in[7];
    float* out = (float*)d_out;

    cudaFuncSetAttribute(gemm_qkv_kernel,
        cudaFuncAttributeMaxDynamicSharedMemorySize, GEMM_SMEM_BYTES);
    cudaFuncSetAttribute(gemm_proj_kernel,
        cudaFuncAttributeMaxDynamicSharedMemorySize, GEMM_SMEM_BYTES);
    cudaFuncSetAttribute(attn_kernel,
        cudaFuncAttributeMaxDynamicSharedMemorySize, ATTN_SMEM_BYTES);

    // pre-conversion passes (independent; overlap on stream)
    cvt_w_kernel<<<144, 256>>>(qkv_w, o_w);
    cvt_x_kernel<<<9408, 256>>>(x);
    combine_bias_kernel<<<dim3((NNP + 255) / 256, NHEADS, NWIN), 256>>>(
        bias_table, rel_index, mask);

    // QKV: M = 200704 (784 tiles of 256), Ncols = 576 (9 tiles of 64)
    gemm_qkv_kernel<<<dim3(9, 784), 256, GEMM_SMEM_BYTES>>>(qkv_b);

    // Attention: one CTA per (b, h)
    attn_kernel<<<BATCH * NHEADS, 128, ATTN_SMEM_BYTES>>>();

    // Projection: Ncols = 192 (3 tiles of 64)
    gemm_proj_kernel<<<dim3(3, 784), 256, GEMM_SMEM_BYTES>>>(o_b, out);
}

// round 12
// speedup vs baseline: 1.2543x; 1.0967x over previous
#include <cuda_runtime.h>
#include <cstddef>
#include <cstdint>

// Problem constants
#define BATCH   2048
#define NTOK    98
#define EMB     192
#define NHEADS  6
#define HDIM    32
#define NWIN    64
#define NN      (NTOK*NTOK)        // 9604
#define NCP     112                // padded key/col dim for attention tiles
#define NNP     (NTOK*NCP)         // 10976 padded bm row block
#define MROWS   (BATCH*NTOK)       // 200704

// Scratch (device globals — no allocation allowed)
__device__ float d_qkv[(size_t)BATCH * 3 * NHEADS * NTOK * HDIM];   // tf32-rounded [b][which][h][n][d]
__device__ float d_attnout[(size_t)BATCH * NTOK * EMB];             // tf32-rounded [b][n][h*32+d]
__device__ float d_bm[(size_t)NHEADS * NWIN * NNP];                 // bias+mask fp32, padded cols
__device__ float d_xt[(size_t)MROWS * EMB];                         // tf32-rounded x
__device__ float d_wq[3 * EMB * EMB];                               // tf32-rounded qkv_w
__device__ float d_wo[EMB * EMB];                                   // tf32-rounded o_w

// ---------------------------------------------------------------------------
// helpers
// ---------------------------------------------------------------------------
__device__ __forceinline__ uint32_t f2tf32(float f) {
    uint32_t u;
    asm("cvt.rna.tf32.f32 %0, %1;" : "=r"(u) : "f"(f));
    return u;
}

__device__ __forceinline__ void mma_tf32(float c[4], const uint32_t a[4], const uint32_t b[2]) {
    asm volatile(
        "mma.sync.aligned.m16n8k8.row.col.f32.tf32.tf32.f32 "
        "{%0,%1,%2,%3},{%4,%5,%6,%7},{%8,%9},{%0,%1,%2,%3};"
        : "+f"(c[0]), "+f"(c[1]), "+f"(c[2]), "+f"(c[3])
        : "r"(a[0]), "r"(a[1]), "r"(a[2]), "r"(a[3]), "r"(b[0]), "r"(b[1]));
}

__device__ __forceinline__ void cp16(uint32_t dst, const void* src) {
    asm volatile("cp.async.cg.shared.global [%0], [%1], 16;" :: "r"(dst), "l"(src));
}
__device__ __forceinline__ void cp_commit() {
    asm volatile("cp.async.commit_group;");
}
template <int N> __device__ __forceinline__ void cp_wait() {
    asm volatile("cp.async.wait_group %0;" :: "n"(N));
}

// ---------------------------------------------------------------------------
// Kernel 0a: convert x -> tf32 bit patterns (float4 grid-stride)
// ---------------------------------------------------------------------------
__global__ void cvt_x_kernel(const float* __restrict__ x) {
    const int n4 = MROWS * EMB / 4;
    for (int i = blockIdx.x * blockDim.x + threadIdx.x; i < n4;
         i += gridDim.x * blockDim.x) {
        float4 v = ((const float4*)x)[i];
        uint4 u = make_uint4(f2tf32(v.x), f2tf32(v.y), f2tf32(v.z), f2tf32(v.w));
        ((uint4*)d_xt)[i] = u;
    }
}

// Kernel 0b: convert weights -> tf32
__global__ void cvt_w_kernel(const float* __restrict__ qkv_w,
                             const float* __restrict__ o_w) {
    const int nq = 3 * EMB * EMB / 4;
    const int no = EMB * EMB / 4;
    for (int i = blockIdx.x * blockDim.x + threadIdx.x; i < nq + no;
         i += gridDim.x * blockDim.x) {
        if (i < nq) {
            float4 v = ((const float4*)qkv_w)[i];
            ((uint4*)d_wq)[i] = make_uint4(f2tf32(v.x), f2tf32(v.y), f2tf32(v.z), f2tf32(v.w));
        } else {
            int j = i - nq;
            float4 v = ((const float4*)o_w)[j];
            ((uint4*)d_wo)[j] = make_uint4(f2tf32(v.x), f2tf32(v.y), f2tf32(v.z), f2tf32(v.w));
        }
    }
}

// ---------------------------------------------------------------------------
// Kernel 1: combine bias + mask with column padding to NCP
// ---------------------------------------------------------------------------
__global__ void combine_bias_kernel(const float* __restrict__ table,
                                    const int* __restrict__ rel,
                                    const float* __restrict__ mask) {
    const int h = blockIdx.y;
    const int w = blockIdx.z;
    const int idx = blockIdx.x * blockDim.x + threadIdx.x;
    if (idx >= NNP) return;
    const int i = idx / NCP;
    const int j = idx - i * NCP;
    float v = -1e30f;
    if (j < NTOK)
        v = table[rel[i * NTOK + j] * NHEADS + h] + mask[(size_t)w * NN + i * NTOK + j];
    d_bm[((size_t)(h * NWIN + w)) * NNP + idx] = v;
}

// ---------------------------------------------------------------------------
// tf32 tensor-core GEMM, inputs pre-converted to tf32 in gmem.
// Block 256x64, K-tile 32, double-buffered cp.async.
// Position-paired fragments: mma slot c <- smem pos 2c, slot c+4 <- pos 2c+1
// (consistent on A and B sides, so the k-sum is unchanged). Each fragment
// pair is one LDS.64; stride 40 makes all frag loads conflict-free.
// ---------------------------------------------------------------------------
#define KTILE 32
#define NKIT  6
#define ASTR  40
#define BSTR  40
#define AS_FLOATS (256 * ASTR)   // 10240
#define BS_FLOATS (64 * BSTR)    // 2560
#define GEMM_SMEM_BYTES ((AS_FLOATS + BS_FLOATS) * 2 * 4)  // 102400

__device__ __forceinline__ void g_load_tiles(const float* __restrict__ A,
                                             const float* __restrict__ W,
                                             float* As, float* Bs,
                                             int m0, int n0, int kt, int tid) {
    const int r = tid >> 3;
    const int q = tid & 7;
    uint32_t as_base = (uint32_t)__cvta_generic_to_shared(As);
    uint32_t bs_base = (uint32_t)__cvta_generic_to_shared(Bs);
    #pragma unroll
    for (int it = 0; it < 8; it++) {
        int m = r + it * 32;
        cp16(as_base + (uint32_t)(m * ASTR + q * 4) * 4,
             A + (size_t)(m0 + m) * EMB + kt + q * 4);
    }
    #pragma unroll
    for (int it = 0; it < 2; it++) {
        int n = r + it * 32;
        cp16(bs_base + (uint32_t)(n * BSTR + q * 4) * 4,
             W + (size_t)(n0 + n) * EMB + kt + q * 4);
    }
    cp_commit();
}

__device__ __forceinline__ void g_compute(const float* As, const float* Bs,
                                          float acc[4][4][4], int lane,
                                          int wm, int wn) {
    const int g = lane >> 2;
    const int c2 = (lane & 3) * 2;
    #pragma unroll
    for (int ks = 0; ks < KTILE; ks += 8) {
        const int kb = ks + c2;
        uint32_t af[4][4];
        #pragma unroll
        for (int mt = 0; mt < 4; mt++) {
            const float* ap = As + (wm * 64 + mt * 16 + g) * ASTR + kb;
            float2 lo = *(const float2*)ap;
            float2 hi = *(const float2*)(ap + 8 * ASTR);
            af[mt][0] = __float_as_uint(lo.x);
            af[mt][2] = __float_as_uint(lo.y);
            af[mt][1] = __float_as_uint(hi.x);
            af[mt][3] = __float_as_uint(hi.y);
        }
        uint32_t bf[4][2];
        #pragma unroll
        for (int nt = 0; nt < 4; nt++) {
            const float* bp = Bs + (wn * 32 + nt * 8 + g) * BSTR + kb;
            float2 bb = *(const float2*)bp;
            bf[nt][0] = __float_as_uint(bb.x);
            bf[nt][1] = __float_as_uint(bb.y);
        }
        #pragma unroll
        for (int mt = 0; mt < 4; mt++)
            #pragma unroll
            for (int nt = 0; nt < 4; nt++)
                mma_tf32(acc[mt][nt], af[mt], bf[nt]);
    }
}

// QKV variant: epilogue rounds (acc + bias) to tf32 and permutes into d_qkv
__global__ __launch_bounds__(256, 2) void gemm_qkv_kernel(
    const float* __restrict__ bias) {
    extern __shared__ float sm[];
    float* As[2] = { sm, sm + AS_FLOATS };
    float* Bs[2] = { sm + 2 * AS_FLOATS, sm + 2 * AS_FLOATS + BS_FLOATS };

    const int tid = threadIdx.x;
    const int lane = tid & 31;
    const int wid = tid >> 5;
    const int wm = wid >> 1;
    const int wn = wid & 1;
    const int m0 = blockIdx.y * 256;
    const int n0 = blockIdx.x * 64;

    float acc[4][4][4];
    #pragma unroll
    for (int mt = 0; mt < 4; mt++)
        #pragma unroll
        for (int nt = 0; nt < 4; nt++)
            #pragma unroll
            for (int r = 0; r < 4; r++) acc[mt][nt][r] = 0.f;

    const float* A = d_xt;
    const float* W = d_wq;
    g_load_tiles(A, W, As[0], Bs[0], m0, n0, 0, tid);
    g_load_tiles(A, W, As[1], Bs[1], m0, n0, KTILE, tid);

    #pragma unroll
    for (int it = 0; it < NKIT; it++) {
        if (it < NKIT - 1) cp_wait<1>(); else cp_wait<0>();
        __syncthreads();
        g_compute(As[it & 1], Bs[it & 1], acc, lane, wm, wn);
        __syncthreads();
        if (it + 2 < NKIT)
            g_load_tiles(A, W, As[it & 1], Bs[it & 1], m0, n0, (it + 2) * KTILE, tid);
    }

    #pragma unroll
    for (int mt = 0; mt < 4; mt++) {
        #pragma unroll
        for (int half = 0; half < 2; half++) {
            int mg = m0 + wm * 64 + mt * 16 + (lane >> 2) + half * 8;
            int bb = mg / NTOK;
            int nn = mg - bb * NTOK;
            #pragma unroll
            for (int nt = 0; nt < 4; nt++) {
                int c = n0 + wn * 32 + nt * 8 + (lane & 3) * 2;
                int which = c / EMB;
                int rem = c - which * EMB;
                int h = rem >> 5;
                int d = rem & 31;
                size_t dst = ((((size_t)bb * 3 + which) * NHEADS + h) * NTOK + nn) * HDIM + d;
                float v0 = __uint_as_float(f2tf32(acc[mt][nt][half * 2 + 0] + bias[c]));
                float v1 = __uint_as_float(f2tf32(acc[mt][nt][half * 2 + 1] + bias[c + 1]));
                *(float2*)&d_qkv[dst] = make_float2(v0, v1);
            }
        }
    }
}

// Projection variant: fp32 store to final output
__global__ __launch_bounds__(256, 2) void gemm_proj_kernel(
    const float* __restrict__ bias, float* __restrict__ out) {
    extern __shared__ float sm[];
    float* As[2] = { sm, sm + AS_FLOATS };
    float* Bs[2] = { sm + 2 * AS_FLOATS, sm + 2 * AS_FLOATS + BS_FLOATS };

    const int tid = threadIdx.x;
    const int lane = tid & 31;
    const int wid = tid >> 5;
    const int wm = wid >> 1;
    const int wn = wid & 1;
    const int m0 = blockIdx.y * 256;
    const int n0 = blockIdx.x * 64;

    float acc[4][4][4];
    #pragma unroll
    for (int mt = 0; mt < 4; mt++)
        #pragma unroll
        for (int nt = 0; nt < 4; nt++)
            #pragma unroll
            for (int r = 0; r < 4; r++) acc[mt][nt][r] = 0.f;

    const float* A = d_attnout;
    const float* W = d_wo;
    g_load_tiles(A, W, As[0], Bs[0], m0, n0, 0, tid);
    g_load_tiles(A, W, As[1], Bs[1], m0, n0, KTILE, tid);

    #pragma unroll
    for (int it = 0; it < NKIT; it++) {
        if (it < NKIT - 1) cp_wait<1>(); else cp_wait<0>();
        __syncthreads();
        g_compute(As[it & 1], Bs[it & 1], acc, lane, wm, wn);
        __syncthreads();
        if (it + 2 < NKIT)
            g_load_tiles(A, W, As[it & 1], Bs[it & 1], m0, n0, (it + 2) * KTILE, tid);
    }

    #pragma unroll
    for (int mt = 0; mt < 4; mt++) {
        #pragma unroll
        for (int half = 0; half < 2; half++) {
            int mg = m0 + wm * 64 + mt * 16 + (lane >> 2) + half * 8;
            #pragma unroll
            for (int nt = 0; nt < 4; nt++) {
                int c = n0 + wn * 32 + nt * 8 + (lane & 3) * 2;
                float v0 = acc[mt][nt][half * 2 + 0] + bias[c];
                float v1 = acc[mt][nt][half * 2 + 1] + bias[c + 1];
                *(float2*)&out[(size_t)mg * EMB + c] = make_float2(v0, v1);
            }
        }
    }
}

// ---------------------------------------------------------------------------
// Kernel 3: tensor-core attention. One CTA (128 thr, 4 warps) per (b, h).
// Position-paired fragments throughout: QK^T frag pairs are LDS.64, and the
// P c-frag (cols {2c,2c+1}) is ALREADY the position-paired a-frag for PV —
// the shfl permutation disappears entirely (register rename + cvt only).
// ---------------------------------------------------------------------------
#define QSTR 40
#define KSTR 40
#define VSTR 36
#define SQ_FLOATS (128 * QSTR)       // 5120
#define SK_FLOATS (NCP * KSTR)       // 4480
#define SV_FLOATS (NCP * VSTR)       // 4032
#define ATTN_SMEM_BYTES ((SQ_FLOATS + SK_FLOATS + SV_FLOATS) * 4)  // 54528

__global__ __launch_bounds__(128, 2) void attn_kernel() {
    extern __shared__ float sh[];
    float* sQ  = sh;
    float* sK  = sQ + SQ_FLOATS;
    float* sV  = sK + SK_FLOATS;

    const int t = threadIdx.x;
    const int lane = t & 31;
    const int w4 = t >> 5;          // warp 0..3

    const int bh = blockIdx.x;
    const int b = bh / NHEADS;
    const int h = bh - b * NHEADS;
    const int win = b & (NWIN - 1);

    const size_t base = (((size_t)b * 3) * NHEADS + h) * (NTOK * HDIM);
    const float* qg = d_qkv + base;
    const float* kg = qg + (size_t)NHEADS * NTOK * HDIM;
    const float* vg = qg + 2 * (size_t)NHEADS * NTOK * HDIM;
    const float* bmg = d_bm + (size_t)(h * NWIN + win) * NNP;

    // ---- stage Q/K/V via cp.async (already tf32), zero pad rows ----
    {
        uint32_t uQ = (uint32_t)__cvta_generic_to_shared(sQ);
        uint32_t uK = (uint32_t)__cvta_generic_to_shared(sK);
        uint32_t uV = (uint32_t)__cvta_generic_to_shared(sV);
        for (int idx = t; idx < NTOK * 8; idx += 128) {
            int r = idx >> 3, q = (idx & 7) * 4;
            cp16(uQ + (uint32_t)(r * QSTR + q) * 4, qg + r * HDIM + q);
            cp16(uK + (uint32_t)(r * KSTR + q) * 4, kg + r * HDIM + q);
            cp16(uV + (uint32_t)(r * VSTR + q) * 4, vg + r * HDIM + q);
        }
        cp_commit();
        float4 z = make_float4(0.f, 0.f, 0.f, 0.f);
        for (int idx = t; idx < 30 * 8; idx += 128) {
            int r = 98 + (idx >> 3), c = (idx & 7) * 4;
            *(float4*)&sQ[r * QSTR + c] = z;
        }
        for (int idx = t; idx < 14 * 8; idx += 128) {
            int r = 98 + (idx >> 3), c = (idx & 7) * 4;
            *(float4*)&sK[r * KSTR + c] = z;
        }
        for (int idx = t; idx < 14 * 8; idx += 128) {
            int r = 98 + (idx >> 3), c = (idx & 7) * 4;
            *(float4*)&sV[r * VSTR + c] = z;
        }
        cp_wait<0>();
        __syncthreads();
    }

    const int g = lane >> 2;        // quad row
    const int c = lane & 3;         // quad pos
    const int c2 = c * 2;

    // ---- S = Q K^T : c-frags sf[2][14][4], position-paired LDS.64 frags ----
    float sf[2][14][4];
    #pragma unroll
    for (int mt = 0; mt < 2; mt++)
        #pragma unroll
        for (int nt = 0; nt < 14; nt++)
            #pragma unroll
            for (int r = 0; r < 4; r++) sf[mt][nt][r] = 0.f;

    #pragma unroll
    for (int ks = 0; ks < 4; ks++) {
        const int kb = ks * 8 + c2;
        uint32_t af[2][4];
        #pragma unroll
        for (int mt = 0; mt < 2; mt++) {
            const float* ap = sQ + (w4 * 32 + mt * 16 + g) * QSTR + kb;
            float2 lo = *(const float2*)ap;
            float2 hi = *(const float2*)(ap + 8 * QSTR);
            af[mt][0] = __float_as_uint(lo.x);
            af[mt][2] = __float_as_uint(lo.y);
            af[mt][1] = __float_as_uint(hi.x);
            af[mt][3] = __float_as_uint(hi.y);
        }
        #pragma unroll
        for (int nt = 0; nt < 14; nt++) {
            const float* bp = sK + (nt * 8 + g) * KSTR + kb;
            float2 bb = *(const float2*)bp;
            uint32_t bf[2];
            bf[0] = __float_as_uint(bb.x);
            bf[1] = __float_as_uint(bb.y);
            mma_tf32(sf[0][nt], af[0], bf);
            mma_tf32(sf[1][nt], af[1], bf);
        }
    }

    // ---- scale + bias/mask (direct gmem) + row max ----
    const float scale = 0.17677669529663687f;  // 32^-0.5
    float mx[2][2];
    #pragma unroll
    for (int mt = 0; mt < 2; mt++) { mx[mt][0] = -1e30f; mx[mt][1] = -1e30f; }

    #pragma unroll
    for (int mt = 0; mt < 2; mt++) {
        int r0 = w4 * 32 + mt * 16 + g;
        int r0c = min(r0, NTOK - 1);
        int r1c = min(r0 + 8, NTOK - 1);
        const float* bm0 = bmg + (size_t)r0c * NCP;
        const float* bm1 = bmg + (size_t)r1c * NCP;
        #pragma unroll
        for (int nt = 0; nt < 14; nt++) {
            int col = nt * 8 + c2;
            float2 b0 = *(const float2*)&bm0[col];
            float2 b1 = *(const float2*)&bm1[col];
            sf[mt][nt][0] = fmaf(sf[mt][nt][0], scale, b0.x);
            sf[mt][nt][1] = fmaf(sf[mt][nt][1], scale, b0.y);
            sf[mt][nt][2] = fmaf(sf[mt][nt][2], scale, b1.x);
            sf[mt][nt][3] = fmaf(sf[mt][nt][3], scale, b1.y);
            mx[mt][0] = fmaxf(mx[mt][0], fmaxf(sf[mt][nt][0], sf[mt][nt][1]));
            mx[mt][1] = fmaxf(mx[mt][1], fmaxf(sf[mt][nt][2], sf[mt][nt][3]));
        }
    }
    #pragma unroll
    for (int mt = 0; mt < 2; mt++)
        #pragma unroll
        for (int hf = 0; hf < 2; hf++) {
            float v = mx[mt][hf];
            v = fmaxf(v, __shfl_xor_sync(0xffffffffu, v, 1));
            v = fmaxf(v, __shfl_xor_sync(0xffffffffu, v, 2));
            mx[mt][hf] = v;
        }

    // ---- exp + row sum ----
    float sum[2][2] = {{0.f, 0.f}, {0.f, 0.f}};
    #pragma unroll
    for (int mt = 0; mt < 2; mt++)
        #pragma unroll
        for (int nt = 0; nt < 14; nt++) {
            float p0 = __expf(sf[mt][nt][0] - mx[mt][0]);
            float p1 = __expf(sf[mt][nt][1] - mx[mt][0]);
            float p2 = __expf(sf[mt][nt][2] - mx[mt][1]);
            float p3 = __expf(sf[mt][nt][3] - mx[mt][1]);
            sf[mt][nt][0] = p0; sf[mt][nt][1] = p1;
            sf[mt][nt][2] = p2; sf[mt][nt][3] = p3;
            sum[mt][0] += p0 + p1;
            sum[mt][1] += p2 + p3;
        }
    #pragma unroll
    for (int mt = 0; mt < 2; mt++)
        #pragma unroll
        for (int hf = 0; hf < 2; hf++) {
            float v = sum[mt][hf];
            v += __shfl_xor_sync(0xffffffffu, v, 1);
            v += __shfl_xor_sync(0xffffffffu, v, 2);
            sum[mt][hf] = v;
        }

    // ---- O = P V : c-frag IS the position-paired a-frag (rename + cvt) ----
    float of[2][4][4];
    #pragma unroll
    for (int mt = 0; mt < 2; mt++)
        #pragma unroll
        for (int nt = 0; nt < 4; nt++)
            #pragma unroll
            for (int r = 0; r < 4; r++) of[mt][nt][r] = 0.f;

    #pragma unroll
    for (int kt = 0; kt < 14; kt++) {
        uint32_t pa[2][4];
        #pragma unroll
        for (int mt = 0; mt < 2; mt++) {
            pa[mt][0] = f2tf32(sf[mt][kt][0]);   // row g,   pos 2c
            pa[mt][1] = f2tf32(sf[mt][kt][2]);   // row g+8, pos 2c
            pa[mt][2] = f2tf32(sf[mt][kt][1]);   // row g,   pos 2c+1
            pa[mt][3] = f2tf32(sf[mt][kt][3]);   // row g+8, pos 2c+1
        }
        #pragma unroll
        for (int nt = 0; nt < 4; nt++) {
            const float* vp = sV + (kt * 8 + c2) * VSTR + nt * 8 + g;
            uint32_t bf[2];
            bf[0] = __float_as_uint(vp[0]);      // V row pos 2c
            bf[1] = __float_as_uint(vp[VSTR]);   // V row pos 2c+1
            mma_tf32(of[0][nt], pa[0], bf);
            mma_tf32(of[1][nt], pa[1], bf);
        }
    }

    // ---- epilogue: normalize, round to tf32 for proj, store ----
    #pragma unroll
    for (int mt = 0; mt < 2; mt++) {
        #pragma unroll
        for (int hf = 0; hf < 2; hf++) {
            int row = w4 * 32 + mt * 16 + g + hf * 8;
            if (row < NTOK) {
                float inv = 1.f / sum[mt][hf];
                float* op = d_attnout + ((size_t)b * NTOK + row) * EMB + h * HDIM;
                #pragma unroll
                for (int nt = 0; nt < 4; nt++) {
                    int col = nt * 8 + c2;
                    float v0 = __uint_as_float(f2tf32(of[mt][nt][hf * 2 + 0] * inv));
                    float v1 = __uint_as_float(f2tf32(of[mt][nt][hf * 2 + 1] * inv));
                    *(float2*)&op[col] = make_float2(v0, v1);
                }
            }
        }
    }
}

// ---------------------------------------------------------------------------
// Launch
// ---------------------------------------------------------------------------
extern "C" void kernel_launch(void* const* d_in, const int* in_sizes, int n_in,
                              void* d_out, int out_size) {
    const float* x          = (const float*)d_in[0];
    const float* mask       = (const float*)d_in[1];
    const float* qkv_w      = (const float*)d_in[2];
    const float* qkv_b      = (const float*)d_in[3];
    const float* o_w        = (const float*)d_in[4];
    const float* o_b        = (const float*)d_in[5];
    const float* bias_table = (const float*)d_in[6];
    const int*   rel_index  = (const int*)d_in[7];
    float* out = (float*)d_out;

    cudaFuncSetAttribute(gemm_qkv_kernel,
        cudaFuncAttributeMaxDynamicSharedMemorySize, GEMM_SMEM_BYTES);
    cudaFuncSetAttribute(gemm_proj_kernel,
        cudaFuncAttributeMaxDynamicSharedMemorySize, GEMM_SMEM_BYTES);
    cudaFuncSetAttribute(attn_kernel,
        cudaFuncAttributeMaxDynamicSharedMemorySize, ATTN_SMEM_BYTES);

    // pre-conversion passes
    cvt_w_kernel<<<144, 256>>>(qkv_w, o_w);
    cvt_x_kernel<<<9408, 256>>>(x);
    combine_bias_kernel<<<dim3((NNP + 255) / 256, NHEADS, NWIN), 256>>>(
        bias_table, rel_index, mask);

    // QKV: M = 200704 (784 tiles of 256), Ncols = 576 (9 tiles of 64)
    gemm_qkv_kernel<<<dim3(9, 784), 256, GEMM_SMEM_BYTES>>>(qkv_b);

    // Attention: one CTA per (b, h)
    attn_kernel<<<BATCH * NHEADS, 128, ATTN_SMEM_BYTES>>>();

    // Projection: Ncols = 192 (3 tiles of 64)
    gemm_proj_kernel<<<dim3(3, 784), 256, GEMM_SMEM_BYTES>>>(o_b, out);
}

// round 13
// speedup vs baseline: 1.3127x; 1.0465x over previous
#include <cuda_runtime.h>
#include <cstddef>
#include <cstdint>

// Problem constants
#define BATCH   2048
#define NTOK    98
#define EMB     192
#define NHEADS  6
#define HDIM    32
#define NWIN    64
#define NN      (NTOK*NTOK)        // 9604
#define NCP     112                // padded key/col dim for attention tiles
#define NNP     (NTOK*NCP)         // 10976 padded bm row block
#define MROWS   (BATCH*NTOK)       // 200704

// Scratch (device globals — no allocation allowed)
__device__ float d_qkv[(size_t)BATCH * 3 * NHEADS * NTOK * HDIM];   // tf32-rounded [b][which][h][n][d]
__device__ float d_attnout[(size_t)BATCH * NTOK * EMB];             // tf32-rounded [b][n][h*32+d]
__device__ float d_bm[(size_t)NHEADS * NWIN * NNP];                 // bias+mask fp32, padded cols
__device__ float d_xt[(size_t)MROWS * EMB];                         // tf32-rounded x
__device__ float d_wq[3 * EMB * EMB];                               // tf32-rounded qkv_w
__device__ float d_wo[EMB * EMB];                                   // tf32-rounded o_w

// ---------------------------------------------------------------------------
// helpers
// ---------------------------------------------------------------------------
__device__ __forceinline__ uint32_t f2tf32(float f) {
    uint32_t u;
    asm("cvt.rna.tf32.f32 %0, %1;" : "=r"(u) : "f"(f));
    return u;
}

__device__ __forceinline__ void mma_tf32(float c[4], const uint32_t a[4], const uint32_t b[2]) {
    asm volatile(
        "mma.sync.aligned.m16n8k8.row.col.f32.tf32.tf32.f32 "
        "{%0,%1,%2,%3},{%4,%5,%6,%7},{%8,%9},{%0,%1,%2,%3};"
        : "+f"(c[0]), "+f"(c[1]), "+f"(c[2]), "+f"(c[3])
        : "r"(a[0]), "r"(a[1]), "r"(a[2]), "r"(a[3]), "r"(b[0]), "r"(b[1]));
}

__device__ __forceinline__ void cp16(uint32_t dst, const void* src) {
    asm volatile("cp.async.cg.shared.global [%0], [%1], 16;" :: "r"(dst), "l"(src));
}
__device__ __forceinline__ void cp_commit() {
    asm volatile("cp.async.commit_group;");
}
template <int N> __device__ __forceinline__ void cp_wait() {
    asm volatile("cp.async.wait_group %0;" :: "n"(N));
}

// ---------------------------------------------------------------------------
// Kernel 0: convert x, qkv_w, o_w -> tf32 bit patterns (single grid-stride)
// ---------------------------------------------------------------------------
__global__ void cvt_all_kernel(const float* __restrict__ x,
                               const float* __restrict__ qkv_w,
                               const float* __restrict__ o_w) {
    const int nx = MROWS * EMB / 4;        // 9,633,792
    const int nq = 3 * EMB * EMB / 4;      // 27,648
    const int no = EMB * EMB / 4;          // 9,216
    const int total = nx + nq + no;
    for (int i = blockIdx.x * blockDim.x + threadIdx.x; i < total;
         i += gridDim.x * blockDim.x) {
        const float4* src;
        uint4* dst;
        if (i < nx)            { src = (const float4*)x + i;          dst = (uint4*)d_xt + i; }
        else if (i < nx + nq)  { src = (const float4*)qkv_w + (i-nx); dst = (uint4*)d_wq + (i-nx); }
        else                   { src = (const float4*)o_w + (i-nx-nq); dst = (uint4*)d_wo + (i-nx-nq); }
        float4 v = *src;
        *dst = make_uint4(f2tf32(v.x), f2tf32(v.y), f2tf32(v.z), f2tf32(v.w));
    }
}

// ---------------------------------------------------------------------------
// Kernel 1: combine bias + mask with column padding to NCP
// ---------------------------------------------------------------------------
__global__ void combine_bias_kernel(const float* __restrict__ table,
                                    const int* __restrict__ rel,
                                    const float* __restrict__ mask) {
    const int h = blockIdx.y;
    const int w = blockIdx.z;
    const int idx = blockIdx.x * blockDim.x + threadIdx.x;
    if (idx >= NNP) return;
    const int i = idx / NCP;
    const int j = idx - i * NCP;
    float v = -1e30f;
    if (j < NTOK)
        v = table[rel[i * NTOK + j] * NHEADS + h] + mask[(size_t)w * NN + i * NTOK + j];
    d_bm[((size_t)(h * NWIN + w)) * NNP + idx] = v;
}

// ---------------------------------------------------------------------------
// tf32 tensor-core GEMM, inputs pre-converted to tf32 in gmem.
// Block 256x64, K-tile 32, double-buffered cp.async, position-paired LDS.64
// fragments (stride 40, conflict-free).
// ---------------------------------------------------------------------------
#define KTILE 32
#define NKIT  6
#define ASTR  40
#define BSTR  40
#define AS_FLOATS (256 * ASTR)   // 10240
#define BS_FLOATS (64 * BSTR)    // 2560
#define GEMM_SMEM_BYTES ((AS_FLOATS + BS_FLOATS) * 2 * 4)  // 102400

__device__ __forceinline__ void g_load_tiles(const float* __restrict__ A,
                                             const float* __restrict__ W,
                                             float* As, float* Bs,
                                             int m0, int n0, int kt, int tid) {
    const int r = tid >> 3;
    const int q = tid & 7;
    uint32_t as_base = (uint32_t)__cvta_generic_to_shared(As);
    uint32_t bs_base = (uint32_t)__cvta_generic_to_shared(Bs);
    #pragma unroll
    for (int it = 0; it < 8; it++) {
        int m = r + it * 32;
        cp16(as_base + (uint32_t)(m * ASTR + q * 4) * 4,
             A + (size_t)(m0 + m) * EMB + kt + q * 4);
    }
    #pragma unroll
    for (int it = 0; it < 2; it++) {
        int n = r + it * 32;
        cp16(bs_base + (uint32_t)(n * BSTR + q * 4) * 4,
             W + (size_t)(n0 + n) * EMB + kt + q * 4);
    }
    cp_commit();
}

__device__ __forceinline__ void g_compute(const float* As, const float* Bs,
                                          float acc[4][4][4], int lane,
                                          int wm, int wn) {
    const int g = lane >> 2;
    const int c2 = (lane & 3) * 2;
    #pragma unroll
    for (int ks = 0; ks < KTILE; ks += 8) {
        const int kb = ks + c2;
        uint32_t af[4][4];
        #pragma unroll
        for (int mt = 0; mt < 4; mt++) {
            const float* ap = As + (wm * 64 + mt * 16 + g) * ASTR + kb;
            float2 lo = *(const float2*)ap;
            float2 hi = *(const float2*)(ap + 8 * ASTR);
            af[mt][0] = __float_as_uint(lo.x);
            af[mt][2] = __float_as_uint(lo.y);
            af[mt][1] = __float_as_uint(hi.x);
            af[mt][3] = __float_as_uint(hi.y);
        }
        uint32_t bf[4][2];
        #pragma unroll
        for (int nt = 0; nt < 4; nt++) {
            const float* bp = Bs + (wn * 32 + nt * 8 + g) * BSTR + kb;
            float2 bb = *(const float2*)bp;
            bf[nt][0] = __float_as_uint(bb.x);
            bf[nt][1] = __float_as_uint(bb.y);
        }
        #pragma unroll
        for (int mt = 0; mt < 4; mt++)
            #pragma unroll
            for (int nt = 0; nt < 4; nt++)
                mma_tf32(acc[mt][nt], af[mt], bf[nt]);
    }
}

// QKV variant: epilogue rounds (acc + bias) to tf32 and permutes into d_qkv
__global__ __launch_bounds__(256, 2) void gemm_qkv_kernel(
    const float* __restrict__ bias) {
    extern __shared__ float sm[];
    float* As[2] = { sm, sm + AS_FLOATS };
    float* Bs[2] = { sm + 2 * AS_FLOATS, sm + 2 * AS_FLOATS + BS_FLOATS };

    const int tid = threadIdx.x;
    const int lane = tid & 31;
    const int wid = tid >> 5;
    const int wm = wid >> 1;
    const int wn = wid & 1;
    const int m0 = blockIdx.y * 256;
    const int n0 = blockIdx.x * 64;

    float acc[4][4][4];
    #pragma unroll
    for (int mt = 0; mt < 4; mt++)
        #pragma unroll
        for (int nt = 0; nt < 4; nt++)
            #pragma unroll
            for (int r = 0; r < 4; r++) acc[mt][nt][r] = 0.f;

    const float* A = d_xt;
    const float* W = d_wq;
    g_load_tiles(A, W, As[0], Bs[0], m0, n0, 0, tid);
    g_load_tiles(A, W, As[1], Bs[1], m0, n0, KTILE, tid);

    #pragma unroll
    for (int it = 0; it < NKIT; it++) {
        if (it < NKIT - 1) cp_wait<1>(); else cp_wait<0>();
        __syncthreads();
        g_compute(As[it & 1], Bs[it & 1], acc, lane, wm, wn);
        __syncthreads();
        if (it + 2 < NKIT)
            g_load_tiles(A, W, As[it & 1], Bs[it & 1], m0, n0, (it + 2) * KTILE, tid);
    }

    #pragma unroll
    for (int mt = 0; mt < 4; mt++) {
        #pragma unroll
        for (int half = 0; half < 2; half++) {
            int mg = m0 + wm * 64 + mt * 16 + (lane >> 2) + half * 8;
            int bb = mg / NTOK;
            int nn = mg - bb * NTOK;
            #pragma unroll
            for (int nt = 0; nt < 4; nt++) {
                int c = n0 + wn * 32 + nt * 8 + (lane & 3) * 2;
                int which = c / EMB;
                int rem = c - which * EMB;
                int h = rem >> 5;
                int d = rem & 31;
                size_t dst = ((((size_t)bb * 3 + which) * NHEADS + h) * NTOK + nn) * HDIM + d;
                float v0 = __uint_as_float(f2tf32(acc[mt][nt][half * 2 + 0] + bias[c]));
                float v1 = __uint_as_float(f2tf32(acc[mt][nt][half * 2 + 1] + bias[c + 1]));
                *(float2*)&d_qkv[dst] = make_float2(v0, v1);
            }
        }
    }
}

// Projection variant: fp32 store to final output
__global__ __launch_bounds__(256, 2) void gemm_proj_kernel(
    const float* __restrict__ bias, float* __restrict__ out) {
    extern __shared__ float sm[];
    float* As[2] = { sm, sm + AS_FLOATS };
    float* Bs[2] = { sm + 2 * AS_FLOATS, sm + 2 * AS_FLOATS + BS_FLOATS };

    const int tid = threadIdx.x;
    const int lane = tid & 31;
    const int wid = tid >> 5;
    const int wm = wid >> 1;
    const int wn = wid & 1;
    const int m0 = blockIdx.y * 256;
    const int n0 = blockIdx.x * 64;

    float acc[4][4][4];
    #pragma unroll
    for (int mt = 0; mt < 4; mt++)
        #pragma unroll
        for (int nt = 0; nt < 4; nt++)
            #pragma unroll
            for (int r = 0; r < 4; r++) acc[mt][nt][r] = 0.f;

    const float* A = d_attnout;
    const float* W = d_wo;
    g_load_tiles(A, W, As[0], Bs[0], m0, n0, 0, tid);
    g_load_tiles(A, W, As[1], Bs[1], m0, n0, KTILE, tid);

    #pragma unroll
    for (int it = 0; it < NKIT; it++) {
        if (it < NKIT - 1) cp_wait<1>(); else cp_wait<0>();
        __syncthreads();
        g_compute(As[it & 1], Bs[it & 1], acc, lane, wm, wn);
        __syncthreads();
        if (it + 2 < NKIT)
            g_load_tiles(A, W, As[it & 1], Bs[it & 1], m0, n0, (it + 2) * KTILE, tid);
    }

    #pragma unroll
    for (int mt = 0; mt < 4; mt++) {
        #pragma unroll
        for (int half = 0; half < 2; half++) {
            int mg = m0 + wm * 64 + mt * 16 + (lane >> 2) + half * 8;
            #pragma unroll
            for (int nt = 0; nt < 4; nt++) {
                int c = n0 + wn * 32 + nt * 8 + (lane & 3) * 2;
                float v0 = acc[mt][nt][half * 2 + 0] + bias[c];
                float v1 = acc[mt][nt][half * 2 + 1] + bias[c + 1];
                *(float2*)&out[(size_t)mg * EMB + c] = make_float2(v0, v1);
            }
        }
    }
}

// ---------------------------------------------------------------------------
// Kernel 3: tensor-core attention. One CTA (256 thr, 8 warps) per (b, h).
// Each warp owns ONE m16 Q-row tile (8 x 16 = 128 rows) -> per-thread state
// halves vs the 4-warp version (sf[14][4] + of[4][4] ~ 100 regs), giving
// 16 warps/SM at launch_bounds(256,2). Same MMA work, same rounding.
// ---------------------------------------------------------------------------
#define QSTR 40
#define KSTR 40
#define VSTR 36
#define SQ_FLOATS (128 * QSTR)       // 5120
#define SK_FLOATS (NCP * KSTR)       // 4480
#define SV_FLOATS (NCP * VSTR)       // 4032
#define ATTN_SMEM_BYTES ((SQ_FLOATS + SK_FLOATS + SV_FLOATS) * 4)  // 54528
#define ATHREADS 256

__global__ __launch_bounds__(ATHREADS, 2) void attn_kernel() {
    extern __shared__ float sh[];
    float* sQ  = sh;
    float* sK  = sQ + SQ_FLOATS;
    float* sV  = sK + SK_FLOATS;

    const int t = threadIdx.x;
    const int lane = t & 31;
    const int w8 = t >> 5;          // warp 0..7, owns Q-rows [w8*16, w8*16+16)

    const int bh = blockIdx.x;
    const int b = bh / NHEADS;
    const int h = bh - b * NHEADS;
    const int win = b & (NWIN - 1);

    const size_t base = (((size_t)b * 3) * NHEADS + h) * (NTOK * HDIM);
    const float* qg = d_qkv + base;
    const float* kg = qg + (size_t)NHEADS * NTOK * HDIM;
    const float* vg = qg + 2 * (size_t)NHEADS * NTOK * HDIM;
    const float* bmg = d_bm + (size_t)(h * NWIN + win) * NNP;

    // ---- stage Q/K/V via cp.async (already tf32), zero pad rows ----
    {
        uint32_t uQ = (uint32_t)__cvta_generic_to_shared(sQ);
        uint32_t uK = (uint32_t)__cvta_generic_to_shared(sK);
        uint32_t uV = (uint32_t)__cvta_generic_to_shared(sV);
        for (int idx = t; idx < NTOK * 8; idx += ATHREADS) {
            int r = idx >> 3, q = (idx & 7) * 4;
            cp16(uQ + (uint32_t)(r * QSTR + q) * 4, qg + r * HDIM + q);
            cp16(uK + (uint32_t)(r * KSTR + q) * 4, kg + r * HDIM + q);
            cp16(uV + (uint32_t)(r * VSTR + q) * 4, vg + r * HDIM + q);
        }
        cp_commit();
        float4 z = make_float4(0.f, 0.f, 0.f, 0.f);
        for (int idx = t; idx < 30 * 8; idx += ATHREADS) {
            int r = 98 + (idx >> 3), c = (idx & 7) * 4;
            *(float4*)&sQ[r * QSTR + c] = z;
        }
        for (int idx = t; idx < 14 * 8; idx += ATHREADS) {
            int r = 98 + (idx >> 3), c = (idx & 7) * 4;
            *(float4*)&sK[r * KSTR + c] = z;
        }
        for (int idx = t; idx < 14 * 8; idx += ATHREADS) {
            int r = 98 + (idx >> 3), c = (idx & 7) * 4;
            *(float4*)&sV[r * VSTR + c] = z;
        }
        cp_wait<0>();
        __syncthreads();
    }

    const int g = lane >> 2;        // quad row
    const int c2 = (lane & 3) * 2;

    // ---- S = Q K^T : c-frags sf[14][4], position-paired LDS.64 frags ----
    float sf[14][4];
    #pragma unroll
    for (int nt = 0; nt < 14; nt++)
        #pragma unroll
        for (int r = 0; r < 4; r++) sf[nt][r] = 0.f;

    #pragma unroll
    for (int ks = 0; ks < 4; ks++) {
        const int kb = ks * 8 + c2;
        const float* ap = sQ + (w8 * 16 + g) * QSTR + kb;
        float2 lo = *(const float2*)ap;
        float2 hi = *(const float2*)(ap + 8 * QSTR);
        uint32_t af[4];
        af[0] = __float_as_uint(lo.x);
        af[2] = __float_as_uint(lo.y);
        af[1] = __float_as_uint(hi.x);
        af[3] = __float_as_uint(hi.y);
        #pragma unroll
        for (int nt = 0; nt < 14; nt++) {
            const float* bp = sK + (nt * 8 + g) * KSTR + kb;
            float2 bb = *(const float2*)bp;
            uint32_t bf[2];
            bf[0] = __float_as_uint(bb.x);
            bf[1] = __float_as_uint(bb.y);
            mma_tf32(sf[nt], af, bf);
        }
    }

    // ---- scale + bias/mask (direct gmem) + row max ----
    const float scale = 0.17677669529663687f;  // 32^-0.5
    float mx[2] = { -1e30f, -1e30f };
    {
        int r0 = w8 * 16 + g;
        int r0c = min(r0, NTOK - 1);
        int r1c = min(r0 + 8, NTOK - 1);
        const float* bm0 = bmg + (size_t)r0c * NCP;
        const float* bm1 = bmg + (size_t)r1c * NCP;
        #pragma unroll
        for (int nt = 0; nt < 14; nt++) {
            int col = nt * 8 + c2;
            float2 b0 = *(const float2*)&bm0[col];
            float2 b1 = *(const float2*)&bm1[col];
            sf[nt][0] = fmaf(sf[nt][0], scale, b0.x);
            sf[nt][1] = fmaf(sf[nt][1], scale, b0.y);
            sf[nt][2] = fmaf(sf[nt][2], scale, b1.x);
            sf[nt][3] = fmaf(sf[nt][3], scale, b1.y);
            mx[0] = fmaxf(mx[0], fmaxf(sf[nt][0], sf[nt][1]));
            mx[1] = fmaxf(mx[1], fmaxf(sf[nt][2], sf[nt][3]));
        }
    }
    #pragma unroll
    for (int hf = 0; hf < 2; hf++) {
        float v = mx[hf];
        v = fmaxf(v, __shfl_xor_sync(0xffffffffu, v, 1));
        v = fmaxf(v, __shfl_xor_sync(0xffffffffu, v, 2));
        mx[hf] = v;
    }

    // ---- exp + row sum ----
    float sum[2] = { 0.f, 0.f };
    #pragma unroll
    for (int nt = 0; nt < 14; nt++) {
        float p0 = __expf(sf[nt][0] - mx[0]);
        float p1 = __expf(sf[nt][1] - mx[0]);
        float p2 = __expf(sf[nt][2] - mx[1]);
        float p3 = __expf(sf[nt][3] - mx[1]);
        sf[nt][0] = p0; sf[nt][1] = p1;
        sf[nt][2] = p2; sf[nt][3] = p3;
        sum[0] += p0 + p1;
        sum[1] += p2 + p3;
    }
    #pragma unroll
    for (int hf = 0; hf < 2; hf++) {
        float v = sum[hf];
        v += __shfl_xor_sync(0xffffffffu, v, 1);
        v += __shfl_xor_sync(0xffffffffu, v, 2);
        sum[hf] = v;
    }

    // ---- O = P V : c-frag IS the position-paired a-frag (rename + cvt) ----
    float of[4][4];
    #pragma unroll
    for (int nt = 0; nt < 4; nt++)
        #pragma unroll
        for (int r = 0; r < 4; r++) of[nt][r] = 0.f;

    #pragma unroll
    for (int kt = 0; kt < 14; kt++) {
        uint32_t pa[4];
        pa[0] = f2tf32(sf[kt][0]);   // row g,   pos 2c
        pa[1] = f2tf32(sf[kt][2]);   // row g+8, pos 2c
        pa[2] = f2tf32(sf[kt][1]);   // row g,   pos 2c+1
        pa[3] = f2tf32(sf[kt][3]);   // row g+8, pos 2c+1
        #pragma unroll
        for (int nt = 0; nt < 4; nt++) {
            const float* vp = sV + (kt * 8 + c2) * VSTR + nt * 8 + g;
            uint32_t bf[2];
            bf[0] = __float_as_uint(vp[0]);      // V row pos 2c
            bf[1] = __float_as_uint(vp[VSTR]);   // V row pos 2c+1
            mma_tf32(of[nt], pa, bf);
        }
    }

    // ---- epilogue: normalize, round to tf32 for proj, store ----
    #pragma unroll
    for (int hf = 0; hf < 2; hf++) {
        int row = w8 * 16 + g + hf * 8;
        if (row < NTOK) {
            float inv = 1.f / sum[hf];
            float* op = d_attnout + ((size_t)b * NTOK + row) * EMB + h * HDIM;
            #pragma unroll
            for (int nt = 0; nt < 4; nt++) {
                int col = nt * 8 + c2;
                float v0 = __uint_as_float(f2tf32(of[nt][hf * 2 + 0] * inv));
                float v1 = __uint_as_float(f2tf32(of[nt][hf * 2 + 1] * inv));
                *(float2*)&op[col] = make_float2(v0, v1);
            }
        }
    }
}

// ---------------------------------------------------------------------------
// Launch
// ---------------------------------------------------------------------------
extern "C" void kernel_launch(void* const* d_in, const int* in_sizes, int n_in,
                              void* d_out, int out_size) {
    const float* x          = (const float*)d_in[0];
    const float* mask       = (const float*)d_in[1];
    const float* qkv_w      = (const float*)d_in[2];
    const float* qkv_b      = (const float*)d_in[3];
    const float* o_w        = (const float*)d_in[4];
    const float* o_b        = (const float*)d_in[5];
    const float* bias_table = (const float*)d_in[6];
    const int*   rel_index  = (const int*)d_in[7];
    float* out = (float*)d_out;

    cudaFuncSetAttribute(gemm_qkv_kernel,
        cudaFuncAttributeMaxDynamicSharedMemorySize, GEMM_SMEM_BYTES);
    cudaFuncSetAttribute(gemm_proj_kernel,
        cudaFuncAttributeMaxDynamicSharedMemorySize, GEMM_SMEM_BYTES);
    cudaFuncSetAttribute(attn_kernel,
        cudaFuncAttributeMaxDynamicSharedMemorySize, ATTN_SMEM_BYTES);

    // pre-conversion + bias/mask combine
    cvt_all_kernel<<<9472, 256>>>(x, qkv_w, o_w);
    combine_bias_kernel<<<dim3((NNP + 255) / 256, NHEADS, NWIN), 256>>>(
        bias_table, rel_index, mask);

    // QKV: M = 200704 (784 tiles of 256), Ncols = 576 (9 tiles of 64)
    gemm_qkv_kernel<<<dim3(9, 784), 256, GEMM_SMEM_BYTES>>>(qkv_b);

    // Attention: one CTA (8 warps) per (b, h)
    attn_kernel<<<BATCH * NHEADS, ATHREADS, ATTN_SMEM_BYTES>>>();

    // Projection: Ncols = 192 (3 tiles of 64)
    gemm_proj_kernel<<<dim3(3, 784), 256, GEMM_SMEM_BYTES>>>(o_b, out);
}